// round 8
// baseline (speedup 1.0000x reference)
#include <cuda_runtime.h>
#include <math.h>

#define HW 65536
#define C_ 64
#define R_ 8
#define B_ 4

typedef unsigned long long u64;

// ---------------- device scratch (no allocations allowed) ----------------
__device__ float d_partial[16][64];                      // [plane=(b*4+i)][chunk]
__device__ __align__(16) float d_kpT[B_][R_][5][C_];     // [b][r][comp0..3,bias][c]
__device__ __align__(16) float d_wgp[R_][4];             // Wg @ W1
__device__ float d_bgp[R_];                              // Wg @ b1 + bg

// packed f32x2 helpers (sm_10x FFMA2) — carried in 64-bit integer registers
__device__ __forceinline__ u64 f32x2_fma(u64 a, u64 b, u64 c) {
    u64 d;
    asm("fma.rn.f32x2 %0, %1, %2, %3;" : "=l"(d) : "l"(a), "l"(b), "l"(c));
    return d;
}
__device__ __forceinline__ u64 f32x2_dup(float v) {
    u64 d;
    asm("mov.b64 %0, {%1, %1};" : "=l"(d) : "f"(v));
    return d;
}

// ---------------- 1) per-plane partial sums (for global means) ----------------
// 1024 blocks, 1 float4/thread: full-chip latency hiding.
__global__ void __launch_bounds__(256) reduce_kernel(const float* __restrict__ rgb,
                                                     const float* __restrict__ edge) {
    int plane = blockIdx.y;             // 0..15  -> b = plane>>2, i = plane&3
    int b = plane >> 2, i = plane & 3;
    const float* src = (i < 3) ? (rgb + (size_t)(b * 3 + i) * HW)
                               : (edge + (size_t)b * HW);
    int tid = threadIdx.x;
    float4 v = ((const float4*)src)[blockIdx.x * 256 + tid];
    float s = (v.x + v.y) + (v.z + v.w);
#pragma unroll
    for (int off = 16; off; off >>= 1) s += __shfl_down_sync(0xFFFFFFFFu, s, off);
    __shared__ float ws[8];
    if ((tid & 31) == 0) ws[tid >> 5] = s;
    __syncthreads();
    if (tid < 8) {
        float t = ws[tid];
#pragma unroll
        for (int off = 4; off; off >>= 1) t += __shfl_down_sync(0xFFu, t, off);
        if (tid == 0) d_partial[plane][blockIdx.x] = t;
    }
}

// ---------------- 2) fused setup: means -> g -> t -> generated kernel, folded+transposed ----------------
__global__ void __launch_bounds__(256) setup_kernel(
        const float* __restrict__ W1, const float* __restrict__ b1,
        const float* __restrict__ Wk1, const float* __restrict__ bk1,
        const float* __restrict__ Wk2, const float* __restrict__ bk2,
        const float* __restrict__ Wg, const float* __restrict__ bg) {
    __shared__ float m4[4], g[64], tg[8];
    __shared__ float kern[4096];                     // kernel[co*64+ci]
    int b = blockIdx.x >> 3, r = blockIdx.x & 7;
    int tid = threadIdx.x;

    if (tid < 4) {
        float s = 0.f;
#pragma unroll
        for (int ch = 0; ch < 64; ch++) s += d_partial[b * 4 + tid][ch];
        m4[tid] = s * (1.0f / 65536.0f);
    }
    __syncthreads();
    if (tid < 64) {
        g[tid] = b1[tid] + W1[tid * 4 + 0] * m4[0] + W1[tid * 4 + 1] * m4[1]
                         + W1[tid * 4 + 2] * m4[2] + W1[tid * 4 + 3] * m4[3];
    }
    __syncthreads();
    if (tid < 8) {
        int row = r * 8 + tid;
        float a = bk1[row];
#pragma unroll 8
        for (int c = 0; c < 64; c++) a += Wk1[row * 64 + c] * g[c];
        tg[tid] = 1.f / (1.f + expf(-a));
    }
    __syncthreads();

    // generated kernel for (b, r): kern[o] = bk2[r][o] + sum_i tg[i]*Wk2[r][o][i]
    const float4* w2 = (const float4*)(Wk2 + (size_t)r * 4096 * 8);
    const float* bk = bk2 + r * 4096;
    float t0 = tg[0], t1 = tg[1], t2 = tg[2], t3 = tg[3];
    float t4 = tg[4], t5 = tg[5], t6 = tg[6], t7 = tg[7];
#pragma unroll
    for (int it = 0; it < 16; it++) {
        int o = tid + it * 256;
        float4 wa = w2[o * 2], wb = w2[o * 2 + 1];
        kern[o] = bk[o] + t0 * wa.x + t1 * wa.y + t2 * wa.z + t3 * wa.w
                        + t4 * wb.x + t5 * wb.y + t6 * wb.z + t7 * wb.w;
    }
    __syncthreads();

    // fold through W1 (64x4) and b1 (64); write TRANSPOSED: d_kpT[b][r][j][c]
    int c = tid >> 2, j = tid & 3;                   // 64 x 4 threads
    float acc = 0.f;
#pragma unroll 8
    for (int ci = 0; ci < 64; ci++) acc += kern[c * 64 + ci] * W1[ci * 4 + j];
    d_kpT[b][r][j][c] = acc;
    if (j == 0) {
        float ab = 0.f;
#pragma unroll 8
        for (int ci = 0; ci < 64; ci++) ab += kern[c * 64 + ci] * b1[ci];
        d_kpT[b][r][4][c] = ab;
    }

    // folded guide weights (once, in block 0)
    if (blockIdx.x == 0) {
        if (tid >= 64 && tid < 96) {
            int rr = (tid - 64) >> 2, jj = tid & 3;
            float s = 0.f;
            for (int cc = 0; cc < 64; cc++) s += Wg[rr * 64 + cc] * W1[cc * 4 + jj];
            d_wgp[rr][jj] = s;
        } else if (tid >= 96 && tid < 104) {
            int rr = tid - 96;
            float s = bg[rr];
            for (int cc = 0; cc < 64; cc++) s += Wg[rr * 64 + cc] * b1[cc];
            d_bgp[rr] = s;
        }
    }
}

// ---------------- 3) streaming main pass: guide argmax + packed-FFMA2 64x5 matvec ----------------
// 2 pixels/thread, 256 threads/block. Weights transposed [r][k][c] stride 68:
// LDS.128 start bank = (20r + 4k + 4g) mod 32 -> 8 regions cover 32 banks, conflict-free.
__global__ void __launch_bounds__(256) main_kernel(const float* __restrict__ rgb,
                                                   const float* __restrict__ edge,
                                                   float* __restrict__ out) {
    __shared__ __align__(16) float sk[R_][5][68];
    int tid = threadIdx.x;
    int b = blockIdx.y;

    {   // load 8*5*64 = 2560 floats
        const float* src = &d_kpT[b][0][0][0];
#pragma unroll
        for (int it = 0; it < 10; it++) {
            int idx = tid + it * 256;
            int r = idx / 320, rem = idx - r * 320;
            int k = rem >> 6, c = rem & 63;
            sk[r][k][c] = src[idx];
        }
    }

    float4 wg[8]; float bgr[8];
#pragma unroll
    for (int r = 0; r < 8; r++) {
        wg[r] = *(const float4*)d_wgp[r];
        bgr[r] = d_bgp[r];
    }
    __syncthreads();

    int pb = blockIdx.x * 512 + tid * 2;   // 2 consecutive pixels per thread
    const float* base = rgb + (size_t)b * 3 * HW;
    float2 c0 = *(const float2*)(base + pb);
    float2 c1 = *(const float2*)(base + HW + pb);
    float2 c2 = *(const float2*)(base + 2 * HW + pb);
    float2 c3 = *(const float2*)(edge + (size_t)b * HW + pb);
    float xs0[2] = {c0.x, c0.y};
    float xs1[2] = {c1.x, c1.y};
    float xs2[2] = {c2.x, c2.y};
    float xs3[2] = {c3.x, c3.y};

    const float* skbase[2];
#pragma unroll
    for (int j = 0; j < 2; j++) {
        float best = -3.4e38f; int ri = 0;
#pragma unroll
        for (int r = 0; r < 8; r++) {
            float gv = bgr[r] + wg[r].x * xs0[j] + wg[r].y * xs1[j]
                              + wg[r].z * xs2[j] + wg[r].w * xs3[j];
            if (gv > best) { best = gv; ri = r; }   // strict > keeps first max (jnp.argmax)
        }
        skbase[j] = &sk[ri][0][0];
    }

    // duplicate each input component into both halves of a packed f32x2 reg
    u64 xd0[2], xd1[2], xd2[2], xd3[2];
#pragma unroll
    for (int j = 0; j < 2; j++) {
        xd0[j] = f32x2_dup(xs0[j]); xd1[j] = f32x2_dup(xs1[j]);
        xd2[j] = f32x2_dup(xs2[j]); xd3[j] = f32x2_dup(xs3[j]);
    }

    float* op = out + (size_t)b * 64 * HW + pb;
#pragma unroll
    for (int g = 0; g < 16; g++) {          // 4 channels per group
        u64 accA[2], accB[2];               // (ch0,ch1) / (ch2,ch3) packed, per pixel
#pragma unroll
        for (int j = 0; j < 2; j++) {
            const float* p = skbase[j] + 4 * g;
            ulonglong2 w0 = *(const ulonglong2*)(p);          // comp0: ch pairs
            ulonglong2 w1 = *(const ulonglong2*)(p + 68);
            ulonglong2 w2 = *(const ulonglong2*)(p + 136);
            ulonglong2 w3 = *(const ulonglong2*)(p + 204);
            ulonglong2 bb = *(const ulonglong2*)(p + 272);    // bias pairs
            u64 a = f32x2_fma(w0.x, xd0[j], bb.x);
            a = f32x2_fma(w1.x, xd1[j], a);
            a = f32x2_fma(w2.x, xd2[j], a);
            accA[j] = f32x2_fma(w3.x, xd3[j], a);
            u64 bq = f32x2_fma(w0.y, xd0[j], bb.y);
            bq = f32x2_fma(w1.y, xd1[j], bq);
            bq = f32x2_fma(w2.y, xd2[j], bq);
            accB[j] = f32x2_fma(w3.y, xd3[j], bq);
        }
        // unpack halves (free: sub-register access) and store per-channel pixel pairs
        float2 a0 = *(float2*)&accA[0], a1 = *(float2*)&accA[1];
        float2 b0 = *(float2*)&accB[0], b1 = *(float2*)&accB[1];
        float* o = op + (size_t)(4 * g) * HW;
        *(float2*)(o)              = make_float2(a0.x, a1.x);
        *(float2*)(o + HW)         = make_float2(a0.y, a1.y);
        *(float2*)(o + 2 * HW)     = make_float2(b0.x, b1.x);
        *(float2*)(o + 3 * HW)     = make_float2(b0.y, b1.y);
    }
}

// ---------------- launch ----------------
extern "C" void kernel_launch(void* const* d_in, const int* in_sizes, int n_in,
                              void* d_out, int out_size) {
    const float* rgb  = (const float*)d_in[0];
    const float* edge = (const float*)d_in[1];
    const float* W1   = (const float*)d_in[2];
    const float* b1   = (const float*)d_in[3];
    const float* Wk1  = (const float*)d_in[4];
    const float* bk1  = (const float*)d_in[5];
    const float* Wk2  = (const float*)d_in[6];
    const float* bk2  = (const float*)d_in[7];
    const float* Wg   = (const float*)d_in[8];
    const float* bg   = (const float*)d_in[9];
    float* out = (float*)d_out;

    reduce_kernel<<<dim3(64, 16), 256>>>(rgb, edge);
    setup_kernel<<<B_ * R_, 256>>>(W1, b1, Wk1, bk1, Wk2, bk2, Wg, bg);
    main_kernel<<<dim3(128, B_), 256>>>(rgb, edge, out);
}

// round 10
// speedup vs baseline: 1.0499x; 1.0499x over previous
#include <cuda_runtime.h>
#include <math.h>

#define HW 65536
#define C_ 64
#define R_ 8
#define B_ 4

// ---------------- device scratch (no allocations allowed) ----------------
__device__ int d_c1 = 0, d_c2 = 0;                       // grid-sync counters (self-resetting)
__device__ float d_partial[16][16];                      // [plane=(b*4+i)][chunk]
__device__ __align__(16) float d_kp4[B_][R_][C_][4];     // folded kernel @ W1
__device__ float d_kb[B_][R_][C_];                       // folded kernel @ b1
__device__ __align__(16) float d_wgp[R_][4];             // Wg @ W1
__device__ float d_bgp[R_];                              // Wg @ b1 + bg

// ---------------- 1) fused: per-plane partial sums -> grid sync -> kernel generation ----------------
// 256 blocks x 256 threads: all co-resident (2 blocks/SM), so the counter spin is safe.
__global__ void __launch_bounds__(256) setup_fused(
        const float* __restrict__ rgb, const float* __restrict__ edge,
        const float* __restrict__ W1, const float* __restrict__ b1,
        const float* __restrict__ Wk1, const float* __restrict__ bk1,
        const float* __restrict__ Wk2, const float* __restrict__ bk2,
        const float* __restrict__ Wg, const float* __restrict__ bg) {
    int tid = threadIdx.x, bid = blockIdx.x;

    // ---- phase 1: reduce. plane = bid>>4 (0..15), chunk = bid&15 ----
    {
        int plane = bid >> 4, chunk = bid & 15;
        int pb = plane >> 2, i = plane & 3;
        const float* src = (i < 3) ? (rgb + (size_t)(pb * 3 + i) * HW)
                                   : (edge + (size_t)pb * HW);
        const float4* p = (const float4*)src + chunk * 1024;
        float s = 0.f;
#pragma unroll
        for (int k = 0; k < 4; k++) {
            float4 v = p[tid + k * 256];
            s += (v.x + v.y) + (v.z + v.w);
        }
#pragma unroll
        for (int off = 16; off; off >>= 1) s += __shfl_down_sync(0xFFFFFFFFu, s, off);
        __shared__ float ws[8];
        if ((tid & 31) == 0) ws[tid >> 5] = s;
        __syncthreads();
        if (tid == 0) {
            float t = ws[0];
#pragma unroll
            for (int w = 1; w < 8; w++) t += ws[w];
            d_partial[plane][chunk] = t;
            __threadfence();
            atomicAdd(&d_c1, 1);
        }
    }

    // ---- grid sync: wait until all 256 blocks published their partials ----
    if (tid == 0) {
        while (atomicAdd(&d_c1, 0) < 256) __nanosleep(32);
    }
    __syncthreads();
    __threadfence();

    // ---- phase 2: blocks 0..31 generate the folded kernels ----
    if (bid < 32) {
        __shared__ float m4[4], g[64], tg[8];
        __shared__ float kern[4096];
        int b = bid >> 3, r = bid & 7;

        if (tid < 4) {
            float s = 0.f;
#pragma unroll
            for (int ch = 0; ch < 16; ch++) s += d_partial[b * 4 + tid][ch];
            m4[tid] = s * (1.0f / 65536.0f);
        }
        __syncthreads();
        if (tid < 64) {
            g[tid] = b1[tid] + W1[tid * 4 + 0] * m4[0] + W1[tid * 4 + 1] * m4[1]
                             + W1[tid * 4 + 2] * m4[2] + W1[tid * 4 + 3] * m4[3];
        }
        __syncthreads();
        if (tid < 8) {
            int row = r * 8 + tid;
            float a = bk1[row];
#pragma unroll 8
            for (int c = 0; c < 64; c++) a += Wk1[row * 64 + c] * g[c];
            tg[tid] = 1.f / (1.f + expf(-a));
        }
        __syncthreads();

        const float4* w2 = (const float4*)(Wk2 + (size_t)r * 4096 * 8);
        const float* bk = bk2 + r * 4096;
        float t0 = tg[0], t1 = tg[1], t2 = tg[2], t3 = tg[3];
        float t4 = tg[4], t5 = tg[5], t6 = tg[6], t7 = tg[7];
#pragma unroll
        for (int it = 0; it < 16; it++) {
            int o = tid + it * 256;
            float4 wa = w2[o * 2], wb = w2[o * 2 + 1];
            kern[o] = bk[o] + t0 * wa.x + t1 * wa.y + t2 * wa.z + t3 * wa.w
                            + t4 * wb.x + t5 * wb.y + t6 * wb.z + t7 * wb.w;
        }
        __syncthreads();

        int c = tid >> 2, j = tid & 3;                   // 64 x 4 threads
        float acc = 0.f;
#pragma unroll 8
        for (int ci = 0; ci < 64; ci++) acc += kern[c * 64 + ci] * W1[ci * 4 + j];
        d_kp4[b][r][c][j] = acc;
        if (j == 0) {
            float ab = 0.f;
#pragma unroll 8
            for (int ci = 0; ci < 64; ci++) ab += kern[c * 64 + ci] * b1[ci];
            d_kb[b][r][c] = ab;
        }

        if (bid == 0) {   // folded guide weights
            if (tid >= 64 && tid < 96) {
                int rr = (tid - 64) >> 2, jj = tid & 3;
                float s = 0.f;
                for (int cc = 0; cc < 64; cc++) s += Wg[rr * 64 + cc] * W1[cc * 4 + jj];
                d_wgp[rr][jj] = s;
            } else if (tid >= 96 && tid < 104) {
                int rr = tid - 96;
                float s = bg[rr];
                for (int cc = 0; cc < 64; cc++) s += Wg[rr * 64 + cc] * b1[cc];
                d_bgp[rr] = s;
            }
        }
    }

    // ---- reset counters for next (graph-replayed) launch ----
    __syncthreads();
    if (tid == 0) {
        int t = atomicAdd(&d_c2, 1);
        if (t == 255) {          // last block: everyone has passed the c1 spin
            d_c1 = 0;
            __threadfence();
            d_c2 = 0;
        }
    }
}

// ---------------- 2) streaming main pass: 1 px/thread, high occupancy ----------------
// grid (256, 4) x 256 thr = 6.9 blocks/SM; ~40 regs -> ~50 warps/SM resident.
// skp stride 65 float4: LDS.128 bank = (4r + 4c) mod 32 -> 8 regions disjoint, conflict-free.
__global__ void __launch_bounds__(256) main_kernel(const float* __restrict__ rgb,
                                                   const float* __restrict__ edge,
                                                   float* __restrict__ out) {
    __shared__ float4 skp[R_][C_ + 1];
    __shared__ float  skb[R_][C_ + 1];
    __shared__ float4 sgw[R_];
    __shared__ float  sgb[R_];
    int tid = threadIdx.x;
    int b = blockIdx.y;
    int p = blockIdx.x * 256 + tid;

    // issue input loads first (longest latency), hide behind smem fill
    const float* base = rgb + (size_t)b * 3 * HW;
    float x0 = base[p];
    float x1 = base[HW + p];
    float x2 = base[2 * HW + p];
    float x3 = edge[(size_t)b * HW + p];

    const float4* kps = (const float4*)&d_kp4[b][0][0][0];
    const float* kbs = &d_kb[b][0][0];
#pragma unroll
    for (int it = 0; it < 2; it++) {
        int idx = tid + it * 256;
        skp[idx >> 6][idx & 63] = kps[idx];
        skb[idx >> 6][idx & 63] = kbs[idx];
    }
    if (tid < 8) {
        sgw[tid] = *(const float4*)d_wgp[tid];
        sgb[tid] = d_bgp[tid];
    }
    __syncthreads();

    // argmax over 8 regions (strict > keeps first max, matching jnp.argmax)
    float best = -3.4e38f; int ri = 0;
#pragma unroll
    for (int r = 0; r < 8; r++) {
        float4 w = sgw[r];
        float gv = sgb[r] + w.x * x0 + w.y * x1 + w.z * x2 + w.w * x3;
        if (gv > best) { best = gv; ri = r; }
    }

    const float4* wrow = &skp[ri][0];
    const float* brow = &skb[ri][0];
    float* op = out + (size_t)b * 64 * HW + p;
#pragma unroll
    for (int c = 0; c < 64; c++) {
        float4 w = wrow[c];
        op[(size_t)c * HW] = brow[c] + w.x * x0 + w.y * x1 + w.z * x2 + w.w * x3;
    }
}

// ---------------- launch ----------------
extern "C" void kernel_launch(void* const* d_in, const int* in_sizes, int n_in,
                              void* d_out, int out_size) {
    const float* rgb  = (const float*)d_in[0];
    const float* edge = (const float*)d_in[1];
    const float* W1   = (const float*)d_in[2];
    const float* b1   = (const float*)d_in[3];
    const float* Wk1  = (const float*)d_in[4];
    const float* bk1  = (const float*)d_in[5];
    const float* Wk2  = (const float*)d_in[6];
    const float* bk2  = (const float*)d_in[7];
    const float* Wg   = (const float*)d_in[8];
    const float* bg   = (const float*)d_in[9];
    float* out = (float*)d_out;

    setup_fused<<<256, 256>>>(rgb, edge, W1, b1, Wk1, bk1, Wk2, bk2, Wg, bg);
    main_kernel<<<dim3(256, B_), 256>>>(rgb, edge, out);
}